// round 4
// baseline (speedup 1.0000x reference)
#include <cuda_runtime.h>

#define B_ 32
#define T_ 4096
#define D_ 64
#define S_ 64
#define H_ 128
#define EPSV 1e-10f

// g_e padded by 512 floats on each side so prefetch rings load unconditionally.
__device__ __align__(16) float g_e_raw[B_ * T_ * S_ + 1024];
__device__ __align__(16) float g_alpha[B_ * T_ * S_];
__device__ __align__(16) float g_beta[B_ * T_ * S_];
__device__ __align__(16) float g_M[S_ * S_];
__device__ __align__(16) float g_pi[S_];
__device__ __align__(16) float g_margpart[B_ * 16 * S_];

typedef unsigned long long u64;

__device__ __forceinline__ u64 pack2(float x, float y) {
    u64 r; asm("mov.b64 %0, {%1, %2};" : "=l"(r) : "f"(x), "f"(y)); return r;
}
__device__ __forceinline__ void unpack2(u64 v, float& x, float& y) {
    asm("mov.b64 {%0, %1}, %2;" : "=f"(x), "=f"(y) : "l"(v));
}
__device__ __forceinline__ u64 fma2(u64 a, u64 b, u64 c) {
    u64 d; asm("fma.rn.f32x2 %0, %1, %2, %3;" : "=l"(d) : "l"(a), "l"(b), "l"(c)); return d;
}
__device__ __forceinline__ u64 add2(u64 a, u64 b) {
    u64 d; asm("add.rn.f32x2 %0, %1, %2;" : "=l"(d) : "l"(a), "l"(b)); return d;
}

// ---------------- setup ----------------
__global__ void setup_kernel(const float* __restrict__ ltm, const float* __restrict__ lip,
                             const float* __restrict__ lr, const float* __restrict__ lp,
                             float* __restrict__ out_dur) {
    int j = threadIdx.x;
    float row[S_];
    float m = -1e30f;
#pragma unroll
    for (int k = 0; k < S_; k++) {
        float v = (k == j) ? -1e10f : ltm[j * S_ + k];
        row[k] = v;
        m = fmaxf(m, v);
    }
    float s = 0.f;
#pragma unroll
    for (int k = 0; k < S_; k++) { row[k] = expf(row[k] - m); s += row[k]; }
    float inv = 1.f / s;
#pragma unroll
    for (int k = 0; k < S_; k++) g_M[j * S_ + k] = row[k] * inv + EPSV;

    float m2 = -1e30f;
#pragma unroll
    for (int k = 0; k < S_; k++) m2 = fmaxf(m2, lip[k]);
    float s2 = 0.f;
#pragma unroll
    for (int k = 0; k < S_; k++) s2 += expf(lip[k] - m2);
    g_pi[j] = expf(lip[j] - m2) / s2;

    float r = expf(lr[j]);
    float p = 1.f / (1.f + expf(-lp[j]));
    out_dur[j] = r * (1.f - p) / p;
}

// ---------------- emission MLP + softmax (unchanged, passing) ----------------
__global__ void __launch_bounds__(128) mlp_kernel(
    const float* __restrict__ obs,
    const float* __restrict__ W1, const float* __restrict__ b1,
    const float* __restrict__ W2, const float* __restrict__ b2,
    const float* __restrict__ W3, const float* __restrict__ b3) {
    extern __shared__ float sm[];
    float* W1s = sm;
    float* W2s = W1s + D_ * H_;
    float* W3s = W2s + H_ * H_;
    float* b1s = W3s + H_ * S_;
    float* b2s = b1s + H_;
    float* b3s = b2s + H_;
    float* bufs = b3s + S_;

    int tid = threadIdx.x;
    for (int i = tid; i < (D_ * H_) / 4; i += 128)
        ((float4*)W1s)[i] = ((const float4*)W1)[i];
    for (int i = tid; i < (H_ * H_) / 4; i += 128)
        ((float4*)W2s)[i] = ((const float4*)W2)[i];
    for (int i = tid; i < (H_ * S_) / 4; i += 128)
        ((float4*)W3s)[i] = ((const float4*)W3)[i];
    if (tid < H_) { b1s[tid] = b1[tid]; b2s[tid] = b2[tid]; }
    if (tid < S_) b3s[tid] = b3[tid];
    __syncthreads();

    int w = tid >> 5, l = tid & 31;
    float* bufA = bufs + w * 4096;
    float* bufB = bufA + 2048;
    const unsigned FULL = 0xffffffffu;
    float* ge = g_e_raw + 512;

    int rowbase = blockIdx.x * 128 + w * 32;

    for (int g = 0; g < 4; g++) {
        int r0 = rowbase + g * 8;
        __syncwarp();
#pragma unroll
        for (int rr = 0; rr < 8; rr++) {
            float2 xv = *(const float2*)&obs[(size_t)(r0 + rr) * D_ + 2 * l];
            *(float4*)&bufA[rr * 128 + 4 * l] = make_float4(xv.x, xv.x, xv.y, xv.y);
        }
        __syncwarp();

        u64 acc[8][2];
        {
            u64 bias0 = *(const u64*)&b1s[4 * l];
            u64 bias1 = *(const u64*)&b1s[4 * l + 2];
#pragma unroll
            for (int rr = 0; rr < 8; rr++) { acc[rr][0] = bias0; acc[rr][1] = bias1; }
        }
#pragma unroll 4
        for (int kp = 0; kp < 32; kp++) {
            ulonglong2 w0 = *(const ulonglong2*)&W1s[(2 * kp) * H_ + 4 * l];
            ulonglong2 w1 = *(const ulonglong2*)&W1s[(2 * kp + 1) * H_ + 4 * l];
#pragma unroll
            for (int rr = 0; rr < 8; rr++) {
                ulonglong2 xq = *(const ulonglong2*)&bufA[rr * 128 + 4 * kp];
                acc[rr][0] = fma2(xq.x, w0.x, acc[rr][0]);
                acc[rr][1] = fma2(xq.x, w0.y, acc[rr][1]);
                acc[rr][0] = fma2(xq.y, w1.x, acc[rr][0]);
                acc[rr][1] = fma2(xq.y, w1.y, acc[rr][1]);
            }
        }
#pragma unroll
        for (int rr = 0; rr < 8; rr++) {
            float h0, h1v, h2v, h3;
            unpack2(acc[rr][0], h0, h1v);
            unpack2(acc[rr][1], h2v, h3);
            h0 = fmaxf(h0, 0.f); h1v = fmaxf(h1v, 0.f);
            h2v = fmaxf(h2v, 0.f); h3 = fmaxf(h3, 0.f);
            *(float4*)&bufB[rr * 256 + 8 * l] = make_float4(h0, h0, h1v, h1v);
            *(float4*)&bufB[rr * 256 + 8 * l + 4] = make_float4(h2v, h2v, h3, h3);
        }
        __syncwarp();

        {
            u64 bias0 = *(const u64*)&b2s[4 * l];
            u64 bias1 = *(const u64*)&b2s[4 * l + 2];
#pragma unroll
            for (int rr = 0; rr < 8; rr++) { acc[rr][0] = bias0; acc[rr][1] = bias1; }
        }
#pragma unroll 4
        for (int kp = 0; kp < 64; kp++) {
            ulonglong2 w0 = *(const ulonglong2*)&W2s[(2 * kp) * H_ + 4 * l];
            ulonglong2 w1 = *(const ulonglong2*)&W2s[(2 * kp + 1) * H_ + 4 * l];
#pragma unroll
            for (int rr = 0; rr < 8; rr++) {
                ulonglong2 xq = *(const ulonglong2*)&bufB[rr * 256 + 4 * kp];
                acc[rr][0] = fma2(xq.x, w0.x, acc[rr][0]);
                acc[rr][1] = fma2(xq.x, w0.y, acc[rr][1]);
                acc[rr][0] = fma2(xq.y, w1.x, acc[rr][0]);
                acc[rr][1] = fma2(xq.y, w1.y, acc[rr][1]);
            }
        }
#pragma unroll
        for (int rr = 0; rr < 8; rr++) {
            float h0, h1v, h2v, h3;
            unpack2(acc[rr][0], h0, h1v);
            unpack2(acc[rr][1], h2v, h3);
            h0 = fmaxf(h0, 0.f); h1v = fmaxf(h1v, 0.f);
            h2v = fmaxf(h2v, 0.f); h3 = fmaxf(h3, 0.f);
            *(float4*)&bufA[rr * 256 + 8 * l] = make_float4(h0, h0, h1v, h1v);
            *(float4*)&bufA[rr * 256 + 8 * l + 4] = make_float4(h2v, h2v, h3, h3);
        }
        __syncwarp();

        u64 acc3[8];
        {
            u64 bias = *(const u64*)&b3s[2 * l];
#pragma unroll
            for (int rr = 0; rr < 8; rr++) acc3[rr] = bias;
        }
#pragma unroll 4
        for (int kp = 0; kp < 64; kp++) {
            u64 w0 = *(const u64*)&W3s[(2 * kp) * S_ + 2 * l];
            u64 w1 = *(const u64*)&W3s[(2 * kp + 1) * S_ + 2 * l];
#pragma unroll
            for (int rr = 0; rr < 8; rr++) {
                ulonglong2 xq = *(const ulonglong2*)&bufA[rr * 256 + 4 * kp];
                acc3[rr] = fma2(xq.x, w0, acc3[rr]);
                acc3[rr] = fma2(xq.y, w1, acc3[rr]);
            }
        }

#pragma unroll
        for (int rr = 0; rr < 8; rr++) {
            float z0, z1;
            unpack2(acc3[rr], z0, z1);
            float mx = fmaxf(z0, z1);
#pragma unroll
            for (int off = 16; off; off >>= 1) mx = fmaxf(mx, __shfl_xor_sync(FULL, mx, off));
            float ex = __expf(z0 - mx), ey = __expf(z1 - mx);
            float s = ex + ey;
#pragma unroll
            for (int off = 16; off; off >>= 1) s += __shfl_xor_sync(FULL, s, off);
            float inv = __fdividef(1.f, s);
            *(float2*)&ge[(size_t)(r0 + rr) * S_ + 2 * l] = make_float2(ex * inv, ey * inv);
        }
    }
}

// ---------------- recursions: 2 independent chains per warp ----------------
// 8 blocks x 128 threads = 32 warps. Warp g (= blockIdx*4 + w):
//   g in 0..15 : FORWARD for batches b0=g, b1=g+16 (chains share M-column regs)
//   g in 16..31: BACKWARD for batches b0=g-16, b1=g (chains share M-row regs)
// Lane l owns states l, l+32. The two chains are independent; their instruction
// streams interleave so one chain's latency is hidden by the other's issue.
// Per-chain arithmetic is identical to the previous passing kernel.

#define FCORE(ch, TT, II, PF)                                                    \
    {                                                                            \
        const ulonglong2* v4 = (const ulonglong2*)sv##ch[p];                     \
        u64 A0 = 0, A1 = 0, A2 = 0, A3 = 0;                                      \
        u64 C0 = 0, C1 = 0, C2 = 0, C3 = 0, s0 = 0, s1 = 0;                      \
        _Pragma("unroll")                                                        \
        for (int n = 0; n < 16; n += 2) {                                        \
            ulonglong2 qa = v4[n], qb = v4[n + 1];                               \
            A0 = fma2(qa.x, M0[2 * n], A0);                                      \
            A1 = fma2(qa.y, M0[2 * n + 1], A1);                                  \
            A2 = fma2(qb.x, M0[2 * n + 2], A2);                                  \
            A3 = fma2(qb.y, M0[2 * n + 3], A3);                                  \
            C0 = fma2(qa.x, M1[2 * n], C0);                                      \
            C1 = fma2(qa.y, M1[2 * n + 1], C1);                                  \
            C2 = fma2(qb.x, M1[2 * n + 2], C2);                                  \
            C3 = fma2(qb.y, M1[2 * n + 3], C3);                                  \
            s0 = add2(s0, add2(qa.x, qa.y));                                     \
            s1 = add2(s1, add2(qb.x, qb.y));                                     \
        }                                                                        \
        u64 atA = add2(add2(A0, A1), add2(A2, A3));                              \
        u64 atB = add2(add2(C0, C1), add2(C2, C3));                              \
        u64 st = add2(s0, s1);                                                   \
        float txA, tyA, txB, tyB, sx, sy;                                        \
        unpack2(atA, txA, tyA);                                                  \
        unpack2(atB, txB, tyB);                                                  \
        unpack2(st, sx, sy);                                                     \
        float csum = sx + sy;                                                    \
        float aA = __fdividef((txA + tyA) * enA##ch[II], csum);                  \
        float aB = __fdividef((txB + tyB) * enB##ch[II], csum);                  \
        llacc##ch += (double)__logf(csum);                                       \
        sv##ch[1 - p][l] = aA;                                                   \
        sv##ch[1 - p][l + 32] = aB;                                              \
        ab##ch[(size_t)(TT)*S_ + l] = aA;                                        \
        ab##ch[(size_t)(TT)*S_ + l + 32] = aB;                                   \
        if (PF) {                                                                \
            enA##ch[II] = e##ch[(ptrdiff_t)((TT) + 4) * S_ + l] + EPSV;          \
            enB##ch[II] = e##ch[(ptrdiff_t)((TT) + 4) * S_ + l + 32] + EPSV;     \
        }                                                                        \
    }

#define BCORE(ch, TT, II, PF)                                                    \
    {                                                                            \
        const ulonglong2* v4 = (const ulonglong2*)sv##ch[p];                     \
        u64 A0 = 0, A1 = 0, A2 = 0, A3 = 0;                                      \
        u64 C0 = 0, C1 = 0, C2 = 0, C3 = 0, s0 = 0, s1 = 0;                      \
        _Pragma("unroll")                                                        \
        for (int n = 0; n < 16; n += 2) {                                        \
            ulonglong2 qa = v4[n], qb = v4[n + 1];                               \
            A0 = fma2(qa.x, M0[2 * n], A0);                                      \
            A1 = fma2(qa.y, M0[2 * n + 1], A1);                                  \
            A2 = fma2(qb.x, M0[2 * n + 2], A2);                                  \
            A3 = fma2(qb.y, M0[2 * n + 3], A3);                                  \
            C0 = fma2(qa.x, M1[2 * n], C0);                                      \
            C1 = fma2(qa.y, M1[2 * n + 1], C1);                                  \
            C2 = fma2(qb.x, M1[2 * n + 2], C2);                                  \
            C3 = fma2(qb.y, M1[2 * n + 3], C3);                                  \
            s0 = add2(s0, add2(qa.x, qa.y));                                     \
            s1 = add2(s1, add2(qb.x, qb.y));                                     \
        }                                                                        \
        u64 atA = add2(add2(A0, A1), add2(A2, A3));                              \
        u64 atB = add2(add2(C0, C1), add2(C2, C3));                              \
        u64 st = add2(s0, s1);                                                   \
        float txA, tyA, txB, tyB, sx, sy;                                        \
        unpack2(atA, txA, tyA);                                                  \
        unpack2(atB, txB, tyB);                                                  \
        unpack2(st, sx, sy);                                                     \
        float csum = sx + sy;                                                    \
        float btA = __fdividef(txA + tyA, csum);                                 \
        float btB = __fdividef(txB + tyB, csum);                                 \
        bb##ch[(size_t)(TT)*S_ + l] = btA;                                       \
        bb##ch[(size_t)(TT)*S_ + l + 32] = btB;                                  \
        sv##ch[1 - p][l] = btA * enA##ch[II];                                    \
        sv##ch[1 - p][l + 32] = btB * enB##ch[II];                               \
        if (PF) {                                                                \
            enA##ch[II] = e##ch[(ptrdiff_t)((TT)-4) * S_ + l] + EPSV;            \
            enB##ch[II] = e##ch[(ptrdiff_t)((TT)-4) * S_ + l + 32] + EPSV;       \
        }                                                                        \
    }

#define FSTEP2(TT, II, PF) \
    FCORE(0, TT, II, PF) FCORE(1, TT, II, PF) __syncwarp(); p ^= 1;
#define BSTEP2(TT, II, PF) \
    BCORE(0, TT, II, PF) BCORE(1, TT, II, PF) __syncwarp(); p ^= 1;

__global__ void __launch_bounds__(128, 1) recursion_kernel(float* __restrict__ out_ll) {
    __shared__ __align__(16) float sv[4][2][2][S_];  // [warp][chain][pingpong][S]
    int w = threadIdx.x >> 5, l = threadIdx.x & 31;
    int g = blockIdx.x * 4 + w;  // 0..31
    bool isbwd = g >= 16;
    int b0 = isbwd ? (g - 16) : g;
    int b1 = b0 + 16;
    float (*sv0)[S_] = sv[w][0];
    float (*sv1)[S_] = sv[w][1];
    const float* e0 = g_e_raw + 512 + (size_t)b0 * T_ * S_;
    const float* e1 = g_e_raw + 512 + (size_t)b1 * T_ * S_;

    u64 M0[32], M1[32];
    if (!isbwd) {
#pragma unroll
        for (int k = 0; k < 32; k++) {
            M0[k] = pack2(g_M[(2 * k) * S_ + l], g_M[(2 * k + 1) * S_ + l]);
            M1[k] = pack2(g_M[(2 * k) * S_ + l + 32], g_M[(2 * k + 1) * S_ + l + 32]);
        }
    } else {
#pragma unroll
        for (int k = 0; k < 32; k++) {
            M0[k] = *(const u64*)&g_M[l * S_ + 2 * k];
            M1[k] = *(const u64*)&g_M[(l + 32) * S_ + 2 * k];
        }
    }

    if (!isbwd) {
        float* ab0 = g_alpha + (size_t)b0 * T_ * S_;
        float* ab1 = g_alpha + (size_t)b1 * T_ * S_;
        {
            float x0 = g_pi[l] * e0[l];
            float y0 = g_pi[l + 32] * e0[l + 32];
            float x1 = g_pi[l] * e1[l];
            float y1 = g_pi[l + 32] * e1[l + 32];
            sv0[0][l] = x0; sv0[0][l + 32] = y0;
            sv1[0][l] = x1; sv1[0][l + 32] = y1;
            ab0[l] = x0; ab0[l + 32] = y0;
            ab1[l] = x1; ab1[l + 32] = y1;
        }
        double llacc0 = 0.0, llacc1 = 0.0;
        float enA0[4], enB0[4], enA1[4], enB1[4];
#pragma unroll
        for (int i = 0; i < 4; i++) {
            enA0[i] = e0[(size_t)(1 + i) * S_ + l] + EPSV;
            enB0[i] = e0[(size_t)(1 + i) * S_ + l + 32] + EPSV;
            enA1[i] = e1[(size_t)(1 + i) * S_ + l] + EPSV;
            enB1[i] = e1[(size_t)(1 + i) * S_ + l + 32] + EPSV;
        }
        __syncwarp();
        int p = 0;
        for (int gg = 0; gg < 1023; gg++) {
            int t0 = 1 + 4 * gg;
            FSTEP2(t0, 0, 1)
            FSTEP2(t0 + 1, 1, 1)
            FSTEP2(t0 + 2, 2, 1)
            FSTEP2(t0 + 3, 3, 1)
        }
        FSTEP2(T_ - 3, 0, 0)
        FSTEP2(T_ - 2, 1, 0)
        FSTEP2(T_ - 1, 2, 0)

        float fs0 = 0.f, fs1 = 0.f;
#pragma unroll
        for (int k = 0; k < S_; k++) { fs0 += sv0[p][k]; fs1 += sv1[p][k]; }
        llacc0 += (double)__logf(fs0);
        llacc1 += (double)__logf(fs1);
        if (l == 0) {
            out_ll[b0] = (float)llacc0;
            out_ll[b1] = (float)llacc1;
        }
    } else {
        float* bb0 = g_beta + (size_t)b0 * T_ * S_;
        float* bb1 = g_beta + (size_t)b1 * T_ * S_;
        bb0[(size_t)(T_ - 1) * S_ + l] = 1.f;
        bb0[(size_t)(T_ - 1) * S_ + l + 32] = 1.f;
        bb1[(size_t)(T_ - 1) * S_ + l] = 1.f;
        bb1[(size_t)(T_ - 1) * S_ + l + 32] = 1.f;
        sv0[0][l] = e0[(size_t)(T_ - 1) * S_ + l] + EPSV;
        sv0[0][l + 32] = e0[(size_t)(T_ - 1) * S_ + l + 32] + EPSV;
        sv1[0][l] = e1[(size_t)(T_ - 1) * S_ + l] + EPSV;
        sv1[0][l + 32] = e1[(size_t)(T_ - 1) * S_ + l + 32] + EPSV;
        float enA0[4], enB0[4], enA1[4], enB1[4];
#pragma unroll
        for (int i = 0; i < 4; i++) {
            enA0[i] = e0[(size_t)(T_ - 2 - i) * S_ + l] + EPSV;
            enB0[i] = e0[(size_t)(T_ - 2 - i) * S_ + l + 32] + EPSV;
            enA1[i] = e1[(size_t)(T_ - 2 - i) * S_ + l] + EPSV;
            enB1[i] = e1[(size_t)(T_ - 2 - i) * S_ + l + 32] + EPSV;
        }
        __syncwarp();
        int p = 0;
        for (int gg = 0; gg < 1023; gg++) {
            int t0 = T_ - 2 - 4 * gg;
            BSTEP2(t0, 0, 1)
            BSTEP2(t0 - 1, 1, 1)
            BSTEP2(t0 - 2, 2, 1)
            BSTEP2(t0 - 3, 3, 1)
        }
        BSTEP2(2, 0, 0)
        BSTEP2(1, 1, 0)
        BSTEP2(0, 2, 0)
    }
}

// ---------------- gamma + marginals (unchanged) ----------------
__global__ void __launch_bounds__(256) gamma_kernel(float* __restrict__ out_probs) {
    int b = blockIdx.x >> 4, chunk = blockIdx.x & 15;
    int w = threadIdx.x >> 5, l = threadIdx.x & 31;
    __shared__ float smarg[8][S_];
    const unsigned FULL = 0xffffffffu;
    float mx = 0.f, my = 0.f;
    int tbase = chunk * 256 + w;
    size_t base = (size_t)b * T_ * S_;
#pragma unroll 4
    for (int k = 0; k < 32; k++) {
        int t = tbase + k * 8;
        size_t idx = base + (size_t)t * S_ + 2 * l;
        float2 va = *(const float2*)&g_alpha[idx];
        float2 vb = *(const float2*)&g_beta[idx];
        float px = va.x * vb.x, py = va.y * vb.y;
        float s = px + py;
#pragma unroll
        for (int off = 16; off; off >>= 1) s += __shfl_xor_sync(FULL, s, off);
        float inv = __fdividef(1.f, s);
        px *= inv; py *= inv;
        *(float2*)&out_probs[idx] = make_float2(px, py);
        mx += px; my += py;
    }
    smarg[w][2 * l] = mx;
    smarg[w][2 * l + 1] = my;
    __syncthreads();
    if (threadIdx.x < S_) {
        float s = 0.f;
#pragma unroll
        for (int ww = 0; ww < 8; ww++) s += smarg[ww][threadIdx.x];
        g_margpart[(size_t)blockIdx.x * S_ + threadIdx.x] = s;
    }
}

__global__ void margreduce_kernel(float* __restrict__ out_marg) {
    int i = blockIdx.x * blockDim.x + threadIdx.x;
    int b = i >> 6, j = i & 63;
    float s = 0.f;
#pragma unroll
    for (int c = 0; c < 16; c++) s += g_margpart[(size_t)(b * 16 + c) * S_ + j];
    out_marg[i] = s * (1.f / (float)T_);
}

// ---------------- launch ----------------
extern "C" void kernel_launch(void* const* d_in, const int* in_sizes, int n_in,
                              void* d_out, int out_size) {
    const float* obs = (const float*)d_in[0];
    const float* W1 = (const float*)d_in[1];
    const float* b1 = (const float*)d_in[2];
    const float* W2 = (const float*)d_in[3];
    const float* b2 = (const float*)d_in[4];
    const float* W3 = (const float*)d_in[5];
    const float* b3 = (const float*)d_in[6];
    const float* ltm = (const float*)d_in[7];
    const float* lip = (const float*)d_in[8];
    const float* lr = (const float*)d_in[9];
    const float* lp = (const float*)d_in[10];

    float* out = (float*)d_out;
    float* out_probs = out;
    float* out_marg = out + (size_t)B_ * T_ * S_;
    float* out_dur = out_marg + (size_t)B_ * S_;
    float* out_ll = out_dur + S_;

    const int smem_bytes = (D_ * H_ + H_ * H_ + H_ * S_ + H_ + H_ + S_ + 4 * 4096) * 4;
    cudaFuncSetAttribute(mlp_kernel, cudaFuncAttributeMaxDynamicSharedMemorySize, smem_bytes);

    setup_kernel<<<1, 64>>>(ltm, lip, lr, lp, out_dur);
    mlp_kernel<<<1024, 128, smem_bytes>>>(obs, W1, b1, W2, b2, W3, b3);
    recursion_kernel<<<8, 128>>>(out_ll);
    gamma_kernel<<<512, 256>>>(out_probs);
    margreduce_kernel<<<8, 256>>>(out_marg);
}

// round 6
// speedup vs baseline: 2.2107x; 2.2107x over previous
#include <cuda_runtime.h>

#define B_ 32
#define T_ 4096
#define D_ 64
#define S_ 64
#define H_ 128
#define EPSV 1e-10f

// g_e padded by 512 floats on each side so prefetch rings load unconditionally.
__device__ __align__(16) float g_e_raw[B_ * T_ * S_ + 1024];
__device__ __align__(16) float g_alpha[B_ * T_ * S_];
__device__ __align__(16) float g_beta[B_ * T_ * S_];
__device__ __align__(16) float g_M[S_ * S_];
__device__ __align__(16) float g_pi[S_];
__device__ __align__(16) float g_margpart[B_ * 16 * S_];

typedef unsigned long long u64;

__device__ __forceinline__ u64 pack2(float x, float y) {
    u64 r; asm("mov.b64 %0, {%1, %2};" : "=l"(r) : "f"(x), "f"(y)); return r;
}
__device__ __forceinline__ void unpack2(u64 v, float& x, float& y) {
    asm("mov.b64 {%0, %1}, %2;" : "=f"(x), "=f"(y) : "l"(v));
}
__device__ __forceinline__ u64 fma2(u64 a, u64 b, u64 c) {
    u64 d; asm("fma.rn.f32x2 %0, %1, %2, %3;" : "=l"(d) : "l"(a), "l"(b), "l"(c)); return d;
}
__device__ __forceinline__ u64 add2(u64 a, u64 b) {
    u64 d; asm("add.rn.f32x2 %0, %1, %2;" : "=l"(d) : "l"(a), "l"(b)); return d;
}

// ---------------- setup ----------------
__global__ void setup_kernel(const float* __restrict__ ltm, const float* __restrict__ lip,
                             const float* __restrict__ lr, const float* __restrict__ lp,
                             float* __restrict__ out_dur) {
    int j = threadIdx.x;
    float row[S_];
    float m = -1e30f;
#pragma unroll
    for (int k = 0; k < S_; k++) {
        float v = (k == j) ? -1e10f : ltm[j * S_ + k];
        row[k] = v;
        m = fmaxf(m, v);
    }
    float s = 0.f;
#pragma unroll
    for (int k = 0; k < S_; k++) { row[k] = expf(row[k] - m); s += row[k]; }
    float inv = 1.f / s;
#pragma unroll
    for (int k = 0; k < S_; k++) g_M[j * S_ + k] = row[k] * inv + EPSV;

    float m2 = -1e30f;
#pragma unroll
    for (int k = 0; k < S_; k++) m2 = fmaxf(m2, lip[k]);
    float s2 = 0.f;
#pragma unroll
    for (int k = 0; k < S_; k++) s2 += expf(lip[k] - m2);
    g_pi[j] = expf(lip[j] - m2) / s2;

    float r = expf(lr[j]);
    float p = 1.f / (1.f + expf(-lp[j]));
    out_dur[j] = r * (1.f - p) / p;
}

// ---------------- emission MLP + softmax (unchanged, passing) ----------------
__global__ void __launch_bounds__(128) mlp_kernel(
    const float* __restrict__ obs,
    const float* __restrict__ W1, const float* __restrict__ b1,
    const float* __restrict__ W2, const float* __restrict__ b2,
    const float* __restrict__ W3, const float* __restrict__ b3) {
    extern __shared__ float sm[];
    float* W1s = sm;
    float* W2s = W1s + D_ * H_;
    float* W3s = W2s + H_ * H_;
    float* b1s = W3s + H_ * S_;
    float* b2s = b1s + H_;
    float* b3s = b2s + H_;
    float* bufs = b3s + S_;

    int tid = threadIdx.x;
    for (int i = tid; i < (D_ * H_) / 4; i += 128)
        ((float4*)W1s)[i] = ((const float4*)W1)[i];
    for (int i = tid; i < (H_ * H_) / 4; i += 128)
        ((float4*)W2s)[i] = ((const float4*)W2)[i];
    for (int i = tid; i < (H_ * S_) / 4; i += 128)
        ((float4*)W3s)[i] = ((const float4*)W3)[i];
    if (tid < H_) { b1s[tid] = b1[tid]; b2s[tid] = b2[tid]; }
    if (tid < S_) b3s[tid] = b3[tid];
    __syncthreads();

    int w = tid >> 5, l = tid & 31;
    float* bufA = bufs + w * 4096;
    float* bufB = bufA + 2048;
    const unsigned FULL = 0xffffffffu;
    float* ge = g_e_raw + 512;

    int rowbase = blockIdx.x * 128 + w * 32;

    for (int g = 0; g < 4; g++) {
        int r0 = rowbase + g * 8;
        __syncwarp();
#pragma unroll
        for (int rr = 0; rr < 8; rr++) {
            float2 xv = *(const float2*)&obs[(size_t)(r0 + rr) * D_ + 2 * l];
            *(float4*)&bufA[rr * 128 + 4 * l] = make_float4(xv.x, xv.x, xv.y, xv.y);
        }
        __syncwarp();

        u64 acc[8][2];
        {
            u64 bias0 = *(const u64*)&b1s[4 * l];
            u64 bias1 = *(const u64*)&b1s[4 * l + 2];
#pragma unroll
            for (int rr = 0; rr < 8; rr++) { acc[rr][0] = bias0; acc[rr][1] = bias1; }
        }
#pragma unroll 4
        for (int kp = 0; kp < 32; kp++) {
            ulonglong2 w0 = *(const ulonglong2*)&W1s[(2 * kp) * H_ + 4 * l];
            ulonglong2 w1 = *(const ulonglong2*)&W1s[(2 * kp + 1) * H_ + 4 * l];
#pragma unroll
            for (int rr = 0; rr < 8; rr++) {
                ulonglong2 xq = *(const ulonglong2*)&bufA[rr * 128 + 4 * kp];
                acc[rr][0] = fma2(xq.x, w0.x, acc[rr][0]);
                acc[rr][1] = fma2(xq.x, w0.y, acc[rr][1]);
                acc[rr][0] = fma2(xq.y, w1.x, acc[rr][0]);
                acc[rr][1] = fma2(xq.y, w1.y, acc[rr][1]);
            }
        }
#pragma unroll
        for (int rr = 0; rr < 8; rr++) {
            float h0, h1v, h2v, h3;
            unpack2(acc[rr][0], h0, h1v);
            unpack2(acc[rr][1], h2v, h3);
            h0 = fmaxf(h0, 0.f); h1v = fmaxf(h1v, 0.f);
            h2v = fmaxf(h2v, 0.f); h3 = fmaxf(h3, 0.f);
            *(float4*)&bufB[rr * 256 + 8 * l] = make_float4(h0, h0, h1v, h1v);
            *(float4*)&bufB[rr * 256 + 8 * l + 4] = make_float4(h2v, h2v, h3, h3);
        }
        __syncwarp();

        {
            u64 bias0 = *(const u64*)&b2s[4 * l];
            u64 bias1 = *(const u64*)&b2s[4 * l + 2];
#pragma unroll
            for (int rr = 0; rr < 8; rr++) { acc[rr][0] = bias0; acc[rr][1] = bias1; }
        }
#pragma unroll 4
        for (int kp = 0; kp < 64; kp++) {
            ulonglong2 w0 = *(const ulonglong2*)&W2s[(2 * kp) * H_ + 4 * l];
            ulonglong2 w1 = *(const ulonglong2*)&W2s[(2 * kp + 1) * H_ + 4 * l];
#pragma unroll
            for (int rr = 0; rr < 8; rr++) {
                ulonglong2 xq = *(const ulonglong2*)&bufB[rr * 256 + 4 * kp];
                acc[rr][0] = fma2(xq.x, w0.x, acc[rr][0]);
                acc[rr][1] = fma2(xq.x, w0.y, acc[rr][1]);
                acc[rr][0] = fma2(xq.y, w1.x, acc[rr][0]);
                acc[rr][1] = fma2(xq.y, w1.y, acc[rr][1]);
            }
        }
#pragma unroll
        for (int rr = 0; rr < 8; rr++) {
            float h0, h1v, h2v, h3;
            unpack2(acc[rr][0], h0, h1v);
            unpack2(acc[rr][1], h2v, h3);
            h0 = fmaxf(h0, 0.f); h1v = fmaxf(h1v, 0.f);
            h2v = fmaxf(h2v, 0.f); h3 = fmaxf(h3, 0.f);
            *(float4*)&bufA[rr * 256 + 8 * l] = make_float4(h0, h0, h1v, h1v);
            *(float4*)&bufA[rr * 256 + 8 * l + 4] = make_float4(h2v, h2v, h3, h3);
        }
        __syncwarp();

        u64 acc3[8];
        {
            u64 bias = *(const u64*)&b3s[2 * l];
#pragma unroll
            for (int rr = 0; rr < 8; rr++) acc3[rr] = bias;
        }
#pragma unroll 4
        for (int kp = 0; kp < 64; kp++) {
            u64 w0 = *(const u64*)&W3s[(2 * kp) * S_ + 2 * l];
            u64 w1 = *(const u64*)&W3s[(2 * kp + 1) * S_ + 2 * l];
#pragma unroll
            for (int rr = 0; rr < 8; rr++) {
                ulonglong2 xq = *(const ulonglong2*)&bufA[rr * 256 + 4 * kp];
                acc3[rr] = fma2(xq.x, w0, acc3[rr]);
                acc3[rr] = fma2(xq.y, w1, acc3[rr]);
            }
        }

#pragma unroll
        for (int rr = 0; rr < 8; rr++) {
            float z0, z1;
            unpack2(acc3[rr], z0, z1);
            float mx = fmaxf(z0, z1);
#pragma unroll
            for (int off = 16; off; off >>= 1) mx = fmaxf(mx, __shfl_xor_sync(FULL, mx, off));
            float ex = __expf(z0 - mx), ey = __expf(z1 - mx);
            float s = ex + ey;
#pragma unroll
            for (int off = 16; off; off >>= 1) s += __shfl_xor_sync(FULL, s, off);
            float inv = __fdividef(1.f, s);
            *(float2*)&ge[(size_t)(r0 + rr) * S_ + 2 * l] = make_float2(ex * inv, ey * inv);
        }
    }
}

// ---------------- recursions: 2 warps per chain, 1 state per lane -------------
// 32 blocks x 128 threads. Block b: tids 0-63 = FORWARD chain batch b (bar 1),
// tids 64-127 = BACKWARD chain batch b (bar 2). Lane group j = tid&63 owns state j.
// Normalization every 2nd step only: the per-step scale cancels in gamma, and
// LL telescopes as sum(log c at norm events) + log(sum v_final). Odd ("free")
// steps skip csum, divide, and log entirely.
// Branch-free hot loop: 4x unroll (2 free+2 norm), peeled tail, padded prefetch.

#define NBAR() asm volatile("bar.sync %0, 64;" :: "r"(barid) : "memory")

// Full 64-input matvec: consumes v4[0..15] (all 64 states), Mp[0..31].
#define MATVEC_CORE(EXTRA)                                                       \
    const ulonglong2* v4 = (const ulonglong2*)svc[p];                            \
    u64 A0 = 0, A1 = 0, A2 = 0, A3 = 0;                                          \
    EXTRA                                                                        \
    _Pragma("unroll")                                                            \
    for (int n = 0; n < 16; n += 2) {                                            \
        ulonglong2 qa = v4[n], qb = v4[n + 1];                                   \
        A0 = fma2(qa.x, Mp[2 * n + 0], A0);                                      \
        A1 = fma2(qa.y, Mp[2 * n + 1], A1);                                      \
        A2 = fma2(qb.x, Mp[2 * n + 2], A2);                                      \
        A3 = fma2(qb.y, Mp[2 * n + 3], A3);                                      \
        SUMS                                                                     \
    }

#define SUMS_ON                                                                  \
    s0 = add2(s0, qa.x); s1 = add2(s1, qa.y);                                    \
    s2 = add2(s2, qb.x); s3 = add2(s3, qb.y);
#define SUMS_OFF

// ---- forward: free step (no normalization)
#define FSTEP_F(TT, II, PF)                                                      \
    {                                                                            \
        _Pragma("push_macro(\"SUMS\")")                                          \
        MATVEC_CORE()                                                            \
        u64 at = add2(add2(A0, A1), add2(A2, A3));                               \
        float tx, ty;                                                            \
        unpack2(at, tx, ty);                                                     \
        float a = (tx + ty) * en[II];                                            \
        svc[1 - p][j] = a;                                                       \
        ab[(size_t)(TT)*S_ + j] = a;                                             \
        if (PF) en[II] = eb[(ptrdiff_t)((TT) + 4) * S_ + j] + EPSV;              \
        NBAR();                                                                  \
        p ^= 1;                                                                  \
        _Pragma("pop_macro(\"SUMS\")")                                           \
    }

// ---- forward: normalizing step
#define FSTEP_N(TT, II, PF)                                                      \
    {                                                                            \
        u64 s0 = 0, s1 = 0, s2 = 0, s3 = 0;                                     \
        MATVEC_CORE()                                                            \
        u64 at = add2(add2(A0, A1), add2(A2, A3));                               \
        u64 st = add2(add2(s0, s1), add2(s2, s3));                               \
        float tx, ty, sx, sy;                                                    \
        unpack2(at, tx, ty);                                                     \
        unpack2(st, sx, sy);                                                     \
        float csum = sx + sy;                                                    \
        float a = __fdividef((tx + ty) * en[II], csum);                          \
        llacc += (double)__logf(csum);                                           \
        svc[1 - p][j] = a;                                                       \
        ab[(size_t)(TT)*S_ + j] = a;                                             \
        if (PF) en[II] = eb[(ptrdiff_t)((TT) + 4) * S_ + j] + EPSV;              \
        NBAR();                                                                  \
        p ^= 1;                                                                  \
    }

// ---- backward: free / normalizing steps
#define BSTEP_F(TT, II, PF)                                                      \
    {                                                                            \
        MATVEC_CORE()                                                            \
        u64 at = add2(add2(A0, A1), add2(A2, A3));                               \
        float tx, ty;                                                            \
        unpack2(at, tx, ty);                                                     \
        float bt = tx + ty;                                                      \
        bb[(size_t)(TT)*S_ + j] = bt;                                            \
        svc[1 - p][j] = bt * en[II];                                             \
        if (PF) en[II] = eb[(ptrdiff_t)((TT)-4) * S_ + j] + EPSV;                \
        NBAR();                                                                  \
        p ^= 1;                                                                  \
    }

#define BSTEP_N(TT, II, PF)                                                      \
    {                                                                            \
        u64 s0 = 0, s1 = 0, s2 = 0, s3 = 0;                                     \
        MATVEC_CORE()                                                            \
        u64 at = add2(add2(A0, A1), add2(A2, A3));                               \
        u64 st = add2(add2(s0, s1), add2(s2, s3));                               \
        float tx, ty, sx, sy;                                                    \
        unpack2(at, tx, ty);                                                     \
        unpack2(st, sx, sy);                                                     \
        float csum = sx + sy;                                                    \
        float bt = __fdividef(tx + ty, csum);                                    \
        bb[(size_t)(TT)*S_ + j] = bt;                                            \
        svc[1 - p][j] = bt * en[II];                                             \
        if (PF) en[II] = eb[(ptrdiff_t)((TT)-4) * S_ + j] + EPSV;                \
        NBAR();                                                                  \
        p ^= 1;                                                                  \
    }

__global__ void __launch_bounds__(128, 1) recursion_kernel(float* __restrict__ out_ll) {
    __shared__ __align__(16) float sv[2][2][S_];  // [chain][pingpong][S]
    int tid = threadIdx.x;
    int half = tid >> 6;   // 0 = forward, 1 = backward
    int j = tid & 63;      // state owned by this lane
    int b = blockIdx.x;
    int barid = 1 + half;
    float (*svc)[S_] = sv[half];
    const float* eb = g_e_raw + 512 + (size_t)b * T_ * S_;

    // Mp[k] packs M-entries for input states (2k, 2k+1) feeding output state j:
    //   fwd: column j of M;  bwd: row j of M.
    u64 Mp[32];
    if (half == 0) {
#pragma unroll
        for (int k = 0; k < 32; k++)
            Mp[k] = pack2(g_M[(2 * k) * S_ + j], g_M[(2 * k + 1) * S_ + j]);
    } else {
#pragma unroll
        for (int k = 0; k < 32; k++)
            Mp[k] = *(const u64*)&g_M[j * S_ + 2 * k];
    }

// expansion helper so MATVEC_CORE's SUMS hook resolves per-macro
#define SUMS SUMS_OFF

    if (half == 0) {
        float* ab = g_alpha + (size_t)b * T_ * S_;
        float a0 = g_pi[j] * eb[j];  // t=0 uses raw emission (no EPS)
        svc[0][j] = a0;
        ab[j] = a0;
        double llacc = 0.0;
        float en[4];
#pragma unroll
        for (int i = 0; i < 4; i++) en[i] = eb[(size_t)(1 + i) * S_ + j] + EPSV;
        NBAR();
        int p = 0;
        for (int g = 0; g < 1023; g++) {
            int t0 = 1 + 4 * g;
            FSTEP_F(t0, 0, 1)
#undef SUMS
#define SUMS SUMS_ON
            FSTEP_N(t0 + 1, 1, 1)
#undef SUMS
#define SUMS SUMS_OFF
            FSTEP_F(t0 + 2, 2, 1)
#undef SUMS
#define SUMS SUMS_ON
            FSTEP_N(t0 + 3, 3, 1)
#undef SUMS
#define SUMS SUMS_OFF
        }
        // tail: t = 4093 (free), 4094 (norm), 4095 (free)
        FSTEP_F(T_ - 3, 0, 0)
#undef SUMS
#define SUMS SUMS_ON
        FSTEP_N(T_ - 2, 1, 0)
#undef SUMS
#define SUMS SUMS_OFF
        FSTEP_F(T_ - 1, 2, 0)

        float fs = 0.f;
#pragma unroll
        for (int k = 0; k < S_; k++) fs += svc[p][k];
        llacc += (double)__logf(fs);
        if (j == 0) out_ll[b] = (float)llacc;
    } else {
        float* bb = g_beta + (size_t)b * T_ * S_;
        bb[(size_t)(T_ - 1) * S_ + j] = 1.f;
        svc[0][j] = eb[(size_t)(T_ - 1) * S_ + j] + EPSV;  // u_{T-1}
        float en[4];
#pragma unroll
        for (int i = 0; i < 4; i++) en[i] = eb[(size_t)(T_ - 2 - i) * S_ + j] + EPSV;
        NBAR();
        int p = 0;
        for (int g = 0; g < 1023; g++) {
            int t0 = T_ - 2 - 4 * g;
            BSTEP_F(t0, 0, 1)
#undef SUMS
#define SUMS SUMS_ON
            BSTEP_N(t0 - 1, 1, 1)
#undef SUMS
#define SUMS SUMS_OFF
            BSTEP_F(t0 - 2, 2, 1)
#undef SUMS
#define SUMS SUMS_ON
            BSTEP_N(t0 - 3, 3, 1)
#undef SUMS
#define SUMS SUMS_OFF
        }
        // tail: t = 2 (free), 1 (norm), 0 (free)
        BSTEP_F(2, 0, 0)
#undef SUMS
#define SUMS SUMS_ON
        BSTEP_N(1, 1, 0)
#undef SUMS
#define SUMS SUMS_OFF
        BSTEP_F(0, 2, 0)
    }
#undef SUMS
}

// ---------------- gamma + marginals (unchanged) ----------------
__global__ void __launch_bounds__(256) gamma_kernel(float* __restrict__ out_probs) {
    int b = blockIdx.x >> 4, chunk = blockIdx.x & 15;
    int w = threadIdx.x >> 5, l = threadIdx.x & 31;
    __shared__ float smarg[8][S_];
    const unsigned FULL = 0xffffffffu;
    float mx = 0.f, my = 0.f;
    int tbase = chunk * 256 + w;
    size_t base = (size_t)b * T_ * S_;
#pragma unroll 4
    for (int k = 0; k < 32; k++) {
        int t = tbase + k * 8;
        size_t idx = base + (size_t)t * S_ + 2 * l;
        float2 va = *(const float2*)&g_alpha[idx];
        float2 vb = *(const float2*)&g_beta[idx];
        float px = va.x * vb.x, py = va.y * vb.y;
        float s = px + py;
#pragma unroll
        for (int off = 16; off; off >>= 1) s += __shfl_xor_sync(FULL, s, off);
        float inv = __fdividef(1.f, s);
        px *= inv; py *= inv;
        *(float2*)&out_probs[idx] = make_float2(px, py);
        mx += px; my += py;
    }
    smarg[w][2 * l] = mx;
    smarg[w][2 * l + 1] = my;
    __syncthreads();
    if (threadIdx.x < S_) {
        float s = 0.f;
#pragma unroll
        for (int ww = 0; ww < 8; ww++) s += smarg[ww][threadIdx.x];
        g_margpart[(size_t)blockIdx.x * S_ + threadIdx.x] = s;
    }
}

__global__ void margreduce_kernel(float* __restrict__ out_marg) {
    int i = blockIdx.x * blockDim.x + threadIdx.x;
    int b = i >> 6, j = i & 63;
    float s = 0.f;
#pragma unroll
    for (int c = 0; c < 16; c++) s += g_margpart[(size_t)(b * 16 + c) * S_ + j];
    out_marg[i] = s * (1.f / (float)T_);
}

// ---------------- launch ----------------
extern "C" void kernel_launch(void* const* d_in, const int* in_sizes, int n_in,
                              void* d_out, int out_size) {
    const float* obs = (const float*)d_in[0];
    const float* W1 = (const float*)d_in[1];
    const float* b1 = (const float*)d_in[2];
    const float* W2 = (const float*)d_in[3];
    const float* b2 = (const float*)d_in[4];
    const float* W3 = (const float*)d_in[5];
    const float* b3 = (const float*)d_in[6];
    const float* ltm = (const float*)d_in[7];
    const float* lip = (const float*)d_in[8];
    const float* lr = (const float*)d_in[9];
    const float* lp = (const float*)d_in[10];

    float* out = (float*)d_out;
    float* out_probs = out;
    float* out_marg = out + (size_t)B_ * T_ * S_;
    float* out_dur = out_marg + (size_t)B_ * S_;
    float* out_ll = out_dur + S_;

    const int smem_bytes = (D_ * H_ + H_ * H_ + H_ * S_ + H_ + H_ + S_ + 4 * 4096) * 4;
    cudaFuncSetAttribute(mlp_kernel, cudaFuncAttributeMaxDynamicSharedMemorySize, smem_bytes);

    setup_kernel<<<1, 64>>>(ltm, lip, lr, lp, out_dur);
    mlp_kernel<<<1024, 128, smem_bytes>>>(obs, W1, b1, W2, b2, W3, b3);
    recursion_kernel<<<32, 128>>>(out_ll);
    gamma_kernel<<<512, 256>>>(out_probs);
    margreduce_kernel<<<8, 256>>>(out_marg);
}